// round 14
// baseline (speedup 1.0000x reference)
#include <cuda_runtime.h>
#include <cuda_bf16.h>
#include <cuda_fp16.h>
#include <cstdint>

#define N_NODES 50000
#define N_EDGES 600000
#define D 128
#define SCAN_B 1024
#define NB ((N_NODES + SCAN_B - 1) / SCAN_B)   // 49

// ---------------------------------------------------------------------------
// Scratch (allocation-free rule: __device__ globals)
// ---------------------------------------------------------------------------
__device__ float  g_mean[(size_t)N_NODES * D]; // gather output (fp32)
__device__ __half g_x16[(size_t)N_NODES * D];  // fp16 copy of x (gather1 src)
__device__ __half g_h16[(size_t)N_NODES * D];  // fp16 layer-1 activations
__device__ int    g_deg[N_NODES];
__device__ int    g_cursor[N_NODES];
__device__ int    g_rowptr[N_NODES + 1];
__device__ int    g_bsum[NB];
__device__ int    g_esrc[N_EDGES];

__device__ __forceinline__ float to_tf32(float f) {
    float r;
    asm("cvt.rna.tf32.f32 %0, %1;" : "=f"(r) : "f"(f));
    return r;
}

// ---------------------------------------------------------------------------
// Fused: x -> fp16 copy AND degree zeroing (one launch)
// ---------------------------------------------------------------------------
__global__ void cvt_and_zero(const float* __restrict__ x) {
    int i = blockIdx.x * blockDim.x + threadIdx.x;   // over float4 units
    if (i < (N_NODES * D) / 4) {
        float4 v = __ldg(reinterpret_cast<const float4*>(x) + i);
        __half2 h0 = __floats2half2_rn(v.x, v.y);
        __half2 h1 = __floats2half2_rn(v.z, v.w);
        uint2 u = make_uint2(*reinterpret_cast<uint32_t*>(&h0),
                             *reinterpret_cast<uint32_t*>(&h1));
        reinterpret_cast<uint2*>(g_x16)[i] = u;
    }
    if (i < N_NODES) g_deg[i] = 0;
}

// ---------------------------------------------------------------------------
// CSR build (coalesced full-chip)
// ---------------------------------------------------------------------------
__global__ void hist_kernel(const int* __restrict__ eidx) {
    int e = blockIdx.x * blockDim.x + threadIdx.x;
    if (e < N_EDGES) atomicAdd(&g_deg[__ldg(&eidx[N_EDGES + e])], 1);
}

__global__ void scan_block() {
    __shared__ int wsum[32];
    int tid = threadIdx.x, lane = tid & 31, w = tid >> 5;
    int gid = blockIdx.x * SCAN_B + tid;
    int v = (gid < N_NODES) ? g_deg[gid] : 0;
    int inc = v;
#pragma unroll
    for (int o = 1; o < 32; o <<= 1) {
        int u = __shfl_up_sync(0xffffffffu, inc, o);
        if (lane >= o) inc += u;
    }
    if (lane == 31) wsum[w] = inc;
    __syncthreads();
    if (w == 0) {
        int t = wsum[lane];
        int i2 = t;
#pragma unroll
        for (int o = 1; o < 32; o <<= 1) {
            int u = __shfl_up_sync(0xffffffffu, i2, o);
            if (lane >= o) i2 += u;
        }
        wsum[lane] = i2 - t;   // exclusive warp offsets
    }
    __syncthreads();
    int incl = wsum[w] + inc;
    if (gid < N_NODES) g_rowptr[gid + 1] = incl;
    if (tid == SCAN_B - 1) g_bsum[blockIdx.x] = incl;
}

__global__ void scan_add() {
    __shared__ int s_ex[64];
    int tid = threadIdx.x, lane = tid & 31;
    if (tid < 32) {
        int v0 = (lane < NB) ? g_bsum[lane] : 0;
        int v1 = (32 + lane < NB) ? g_bsum[32 + lane] : 0;
        int i0 = v0, i1 = v1;
#pragma unroll
        for (int o = 1; o < 32; o <<= 1) {
            int u0 = __shfl_up_sync(0xffffffffu, i0, o);
            int u1 = __shfl_up_sync(0xffffffffu, i1, o);
            if (lane >= o) { i0 += u0; i1 += u1; }
        }
        int tot0 = __shfl_sync(0xffffffffu, i0, 31);
        s_ex[lane] = i0 - v0;
        s_ex[32 + lane] = i1 - v1 + tot0;
    }
    __syncthreads();
    int off = s_ex[blockIdx.x];
    int gid = blockIdx.x * SCAN_B + tid;
    if (gid < N_NODES) {
        int rp = g_rowptr[gid + 1] + off;
        g_rowptr[gid + 1] = rp;
        if (gid + 1 < N_NODES) g_cursor[gid + 1] = rp;
    }
    if (gid == 0) { g_rowptr[0] = 0; g_cursor[0] = 0; }
}

__global__ void fill_kernel(const int* __restrict__ eidx) {
    int e = blockIdx.x * blockDim.x + threadIdx.x;
    if (e >= N_EDGES) return;
    int s = __ldg(&eidx[e]);
    int d = __ldg(&eidx[N_EDGES + e]);
    int slot = atomicAdd(&g_cursor[d], 1);
    g_esrc[slot] = s;
}

// ---------------------------------------------------------------------------
// Gather-side mean aggregation over fp16 features: one warp per dst node.
// ---------------------------------------------------------------------------
__device__ __forceinline__ void acc_row(float4& acc, uint2 u) {
    float2 f0 = __half22float2(*reinterpret_cast<__half2*>(&u.x));
    float2 f1 = __half22float2(*reinterpret_cast<__half2*>(&u.y));
    acc.x += f0.x; acc.y += f0.y; acc.z += f1.x; acc.w += f1.y;
}

template <int LAYER>
__global__ void gather_kernel() {
    int warp = (blockIdx.x * blockDim.x + threadIdx.x) >> 5;
    int lane = threadIdx.x & 31;
    if (warp >= N_NODES) return;

    const __half* feat = (LAYER == 1) ? g_x16 : g_h16;

    int beg = __ldg(&g_rowptr[warp]);
    int end = __ldg(&g_rowptr[warp + 1]);

    float4 acc = make_float4(0.f, 0.f, 0.f, 0.f);
    int j = beg;
    for (; j + 4 <= end; j += 4) {
        int s0 = __ldg(&g_esrc[j + 0]);
        int s1 = __ldg(&g_esrc[j + 1]);
        int s2 = __ldg(&g_esrc[j + 2]);
        int s3 = __ldg(&g_esrc[j + 3]);
        uint2 u0 = __ldg(reinterpret_cast<const uint2*>(feat + (size_t)s0 * D) + lane);
        uint2 u1 = __ldg(reinterpret_cast<const uint2*>(feat + (size_t)s1 * D) + lane);
        uint2 u2 = __ldg(reinterpret_cast<const uint2*>(feat + (size_t)s2 * D) + lane);
        uint2 u3 = __ldg(reinterpret_cast<const uint2*>(feat + (size_t)s3 * D) + lane);
        acc_row(acc, u0); acc_row(acc, u1); acc_row(acc, u2); acc_row(acc, u3);
    }
    for (; j < end; j++) {
        int s = __ldg(&g_esrc[j]);
        uint2 u = __ldg(reinterpret_cast<const uint2*>(feat + (size_t)s * D) + lane);
        acc_row(acc, u);
    }

    float inv = 1.0f / fmaxf((float)(end - beg), 1.0f);
    acc.x *= inv; acc.y *= inv; acc.z *= inv; acc.w *= inv;
    reinterpret_cast<float4*>(g_mean + (size_t)warp * D)[lane] = acc;
}

// ---------------------------------------------------------------------------
// tf32 mma.sync GEMM: out = mean @ Wl + feat @ Wr + b (+relu L1)
// CTA = 64 rows x 128 cols -> smem 103 KB -> 2 CTAs/SM: one CTA's staging
// latency is hidden under the other's mma phase (occ-1 was the R13 residual).
// 8 warps in a 4x2 grid, each warp m16 x n64. K=256 via two staged passes.
// ---------------------------------------------------------------------------
#define MROWS 64
#define ASA 132
#define WSB 136
#define TCSM ((MROWS * ASA + 128 * WSB) * 4)   // 103.4 KB

__device__ __forceinline__ void mma_tf32(float c[4], uint32_t a0, uint32_t a1,
                                         uint32_t a2, uint32_t a3,
                                         uint32_t b0, uint32_t b1) {
    asm volatile(
        "mma.sync.aligned.m16n8k8.row.col.f32.tf32.tf32.f32 "
        "{%0,%1,%2,%3}, {%4,%5,%6,%7}, {%8,%9}, {%0,%1,%2,%3};"
        : "+f"(c[0]), "+f"(c[1]), "+f"(c[2]), "+f"(c[3])
        : "r"(a0), "r"(a1), "r"(a2), "r"(a3), "r"(b0), "r"(b1));
}

template <int LAYER>
__global__ void __launch_bounds__(256, 2)
sage_gemm_mma(const float* __restrict__ x_in,
              const float* __restrict__ Wl, const float* __restrict__ Wr,
              const float* __restrict__ bias, float* __restrict__ d_out) {
    extern __shared__ float sm[];
    float* sA = sm;                   // [MROWS][ASA]
    float* sW = sm + MROWS * ASA;     // [128][WSB]

    int tid = threadIdx.x;
    int wid = tid >> 5;
    int lane = tid & 31;
    int gid = lane >> 2;            // 0..7
    int tig = lane & 3;             // 0..3
    int mw = wid >> 1;              // 0..3: m strip of 16 rows
    int nw = wid & 1;               // 0..1: n strip of 64 cols
    int base = blockIdx.x * MROWS;

    float c[8][4];
#pragma unroll
    for (int nt = 0; nt < 8; nt++)
#pragma unroll
        for (int q = 0; q < 4; q++) c[nt][q] = 0.f;

#pragma unroll
    for (int pass = 0; pass < 2; pass++) {
        const float* Wsrc = (pass == 0) ? Wl : Wr;

        if (pass) __syncthreads();   // all warps done reading pass-0 tiles

        // Stage A: MROWS rows x 32 float4 (8 per thread)
        for (int e = tid; e < MROWS * 32; e += 256) {
            int r = e >> 5, c4 = e & 31;
            int g = base + r;
            float4 v = make_float4(0.f, 0.f, 0.f, 0.f);
            if (g < N_NODES) {
                if (pass == 0) {
                    v = __ldg(reinterpret_cast<const float4*>(g_mean + (size_t)g * D) + c4);
                } else if (LAYER == 1) {
                    v = __ldg(reinterpret_cast<const float4*>(x_in + (size_t)g * D) + c4);
                } else {
                    uint2 u = __ldg(reinterpret_cast<const uint2*>(g_h16 + (size_t)g * D) + c4);
                    float2 f0 = __half22float2(*reinterpret_cast<__half2*>(&u.x));
                    float2 f1 = __half22float2(*reinterpret_cast<__half2*>(&u.y));
                    v = make_float4(f0.x, f0.y, f1.x, f1.y);
                }
            }
            v.x = to_tf32(v.x); v.y = to_tf32(v.y);
            v.z = to_tf32(v.z); v.w = to_tf32(v.w);
            *reinterpret_cast<float4*>(sA + r * ASA + c4 * 4) = v;
        }
        // Stage W (row-major [k][n], consumed as col-frag B)
        for (int e = tid; e < 128 * 32; e += 256) {
            int r = e >> 5, c4 = e & 31;
            float4 v = __ldg(reinterpret_cast<const float4*>(Wsrc + (size_t)r * D) + c4);
            v.x = to_tf32(v.x); v.y = to_tf32(v.y);
            v.z = to_tf32(v.z); v.w = to_tf32(v.w);
            *reinterpret_cast<float4*>(sW + r * WSB + c4 * 4) = v;
        }
        __syncthreads();

        const float* Awarp = sA + (mw * 16 + gid) * ASA + tig;
#pragma unroll 4
        for (int ks = 0; ks < 16; ks++) {
            const float* ap = Awarp + ks * 8;
            uint32_t a0 = __float_as_uint(ap[0]);
            uint32_t a1 = __float_as_uint(ap[8 * ASA]);
            uint32_t a2 = __float_as_uint(ap[4]);
            uint32_t a3 = __float_as_uint(ap[8 * ASA + 4]);
            const float* bp = sW + (ks * 8 + tig) * WSB + nw * 64 + gid;
#pragma unroll
            for (int nt = 0; nt < 8; nt++) {
                uint32_t b0 = __float_as_uint(bp[nt * 8]);
                uint32_t b1 = __float_as_uint(bp[4 * WSB + nt * 8]);
                mma_tf32(c[nt], a0, a1, a2, a3, b0, b1);
            }
        }
    }

    // Epilogue: bias (+relu); L1 -> g_h16 (fp16), L2 -> d_out (fp32)
    int row0 = base + mw * 16 + gid;
#pragma unroll
    for (int nt = 0; nt < 8; nt++) {
        int col = nw * 64 + nt * 8 + 2 * tig;
        float2 bb = *reinterpret_cast<const float2*>(bias + col);
        float o0 = c[nt][0] + bb.x, o1 = c[nt][1] + bb.y;
        float o2 = c[nt][2] + bb.x, o3 = c[nt][3] + bb.y;
        if (LAYER == 1) {
            o0 = fmaxf(o0, 0.f); o1 = fmaxf(o1, 0.f);
            o2 = fmaxf(o2, 0.f); o3 = fmaxf(o3, 0.f);
            __half2 p0 = __floats2half2_rn(o0, o1);
            __half2 p1 = __floats2half2_rn(o2, o3);
            if (row0 < N_NODES)
                *reinterpret_cast<__half2*>(g_h16 + (size_t)row0 * D + col) = p0;
            if (row0 + 8 < N_NODES)
                *reinterpret_cast<__half2*>(g_h16 + (size_t)(row0 + 8) * D + col) = p1;
        } else {
            if (row0 < N_NODES)
                *reinterpret_cast<float2*>(d_out + (size_t)row0 * D + col) = make_float2(o0, o1);
            if (row0 + 8 < N_NODES)
                *reinterpret_cast<float2*>(d_out + (size_t)(row0 + 8) * D + col) = make_float2(o2, o3);
        }
    }
}

// ---------------------------------------------------------------------------
extern "C" void kernel_launch(void* const* d_in, const int* in_sizes, int n_in,
                              void* d_out, int out_size) {
    const float* x       = (const float*)d_in[0];
    const int* ei        = (const int*)d_in[1];   // int32 (JAX x64 disabled)
    const float* Wl1     = (const float*)d_in[2];
    const float* Wr1     = (const float*)d_in[3];
    const float* b1      = (const float*)d_in[4];
    const float* Wl2     = (const float*)d_in[5];
    const float* Wr2     = (const float*)d_in[6];
    const float* b2      = (const float*)d_in[7];
    float* out           = (float*)d_out;

    cudaFuncSetAttribute(sage_gemm_mma<1>,
                         cudaFuncAttributeMaxDynamicSharedMemorySize, TCSM);
    cudaFuncSetAttribute(sage_gemm_mma<2>,
                         cudaFuncAttributeMaxDynamicSharedMemorySize, TCSM);

    int eb = (N_EDGES + 255) / 256;
    int gather_blocks = (N_NODES * 32 + 255) / 256;
    int gemm_blocks = (N_NODES + MROWS - 1) / MROWS;

    // fp16 convert + degree zero (1 launch) + CSR build (4 launches)
    cvt_and_zero<<<((N_NODES * D / 4) + 255) / 256, 256>>>(x);
    hist_kernel<<<eb, 256>>>(ei);
    scan_block<<<NB, SCAN_B>>>();
    scan_add<<<NB, SCAN_B>>>();
    fill_kernel<<<eb, 256>>>(ei);

    // Layer 1
    gather_kernel<1><<<gather_blocks, 256>>>();
    sage_gemm_mma<1><<<gemm_blocks, 256, TCSM>>>(x, Wl1, Wr1, b1, out);

    // Layer 2
    gather_kernel<2><<<gather_blocks, 256>>>();
    sage_gemm_mma<2><<<gemm_blocks, 256, TCSM>>>(x, Wl2, Wr2, b2, out);
}

// round 15
// speedup vs baseline: 1.0689x; 1.0689x over previous
#include <cuda_runtime.h>
#include <cuda_bf16.h>
#include <cuda_fp16.h>
#include <cstdint>

#define N_NODES 50000
#define N_PAD   50048          // padded rows so GEMM staging needs no bounds checks
#define N_EDGES 600000
#define D 128
#define SCAN_B 1024
#define NB ((N_NODES + SCAN_B - 1) / SCAN_B)   // 49

// ---------------------------------------------------------------------------
// Scratch (allocation-free rule: __device__ globals; .bss zero-initialized,
// pad rows [50000,50048) are never written -> stay zero, never NaN)
// ---------------------------------------------------------------------------
__device__ float g_mean[(size_t)N_PAD * D];   // gather out, tf32-rounded
__device__ float g_xtf[(size_t)N_PAD * D];    // x, tf32-rounded
__device__ float g_htf[(size_t)N_PAD * D];    // layer-1 activations, tf32-rounded
__device__ float g_Wtf[4 * D * D];            // Wl1,Wr1,Wl2,Wr2 tf32-rounded
__device__ int   g_deg[N_NODES];
__device__ int   g_cursor[N_NODES];
__device__ int   g_rowptr[N_NODES + 1];
__device__ int   g_bsum[NB];
__device__ int   g_esrc[N_EDGES];

__device__ __forceinline__ float to_tf32(float f) {
    float r;
    asm("cvt.rna.tf32.f32 %0, %1;" : "=f"(r) : "f"(f));
    return r;
}

__device__ __forceinline__ void cp16(void* s, const void* g) {
    uint32_t sa = (uint32_t)__cvta_generic_to_shared(s);
    asm volatile("cp.async.cg.shared.global [%0], [%1], 16;"
                 :: "r"(sa), "l"(g) : "memory");
}
#define CP_COMMIT() asm volatile("cp.async.commit_group;" ::: "memory")
#define CP_WAIT0()  asm volatile("cp.async.wait_group 0;" ::: "memory")

// ---------------------------------------------------------------------------
// Prep: round x and all 4 W's to tf32 once; zero degree counters. 1 launch.
// ---------------------------------------------------------------------------
__global__ void prep_kernel(const float* __restrict__ x,
                            const float* __restrict__ Wl1, const float* __restrict__ Wr1,
                            const float* __restrict__ Wl2, const float* __restrict__ Wr2) {
    int i = blockIdx.x * blockDim.x + threadIdx.x;   // float4 units
    const int XN = (N_NODES * D) / 4;                // 1.6M
    if (i < XN) {
        float4 v = __ldg(reinterpret_cast<const float4*>(x) + i);
        v.x = to_tf32(v.x); v.y = to_tf32(v.y);
        v.z = to_tf32(v.z); v.w = to_tf32(v.w);
        reinterpret_cast<float4*>(g_xtf)[i] = v;
    }
    const int WN = D * D / 4;                        // 4096 per matrix
    if (i < 4 * WN) {
        int mat = i / WN, r = i % WN;
        const float* W = (mat == 0) ? Wl1 : (mat == 1) ? Wr1 : (mat == 2) ? Wl2 : Wr2;
        float4 v = __ldg(reinterpret_cast<const float4*>(W) + r);
        v.x = to_tf32(v.x); v.y = to_tf32(v.y);
        v.z = to_tf32(v.z); v.w = to_tf32(v.w);
        reinterpret_cast<float4*>(g_Wtf)[i] = v;
    }
    if (i < N_NODES) g_deg[i] = 0;
}

// ---------------------------------------------------------------------------
// CSR build (coalesced full-chip)
// ---------------------------------------------------------------------------
__global__ void hist_kernel(const int* __restrict__ eidx) {
    int e = blockIdx.x * blockDim.x + threadIdx.x;
    if (e < N_EDGES) atomicAdd(&g_deg[__ldg(&eidx[N_EDGES + e])], 1);
}

__global__ void scan_block() {
    __shared__ int wsum[32];
    int tid = threadIdx.x, lane = tid & 31, w = tid >> 5;
    int gid = blockIdx.x * SCAN_B + tid;
    int v = (gid < N_NODES) ? g_deg[gid] : 0;
    int inc = v;
#pragma unroll
    for (int o = 1; o < 32; o <<= 1) {
        int u = __shfl_up_sync(0xffffffffu, inc, o);
        if (lane >= o) inc += u;
    }
    if (lane == 31) wsum[w] = inc;
    __syncthreads();
    if (w == 0) {
        int t = wsum[lane];
        int i2 = t;
#pragma unroll
        for (int o = 1; o < 32; o <<= 1) {
            int u = __shfl_up_sync(0xffffffffu, i2, o);
            if (lane >= o) i2 += u;
        }
        wsum[lane] = i2 - t;   // exclusive warp offsets
    }
    __syncthreads();
    int incl = wsum[w] + inc;
    if (gid < N_NODES) g_rowptr[gid + 1] = incl;
    if (tid == SCAN_B - 1) g_bsum[blockIdx.x] = incl;
}

__global__ void scan_add() {
    __shared__ int s_ex[64];
    int tid = threadIdx.x, lane = tid & 31;
    if (tid < 32) {
        int v0 = (lane < NB) ? g_bsum[lane] : 0;
        int v1 = (32 + lane < NB) ? g_bsum[32 + lane] : 0;
        int i0 = v0, i1 = v1;
#pragma unroll
        for (int o = 1; o < 32; o <<= 1) {
            int u0 = __shfl_up_sync(0xffffffffu, i0, o);
            int u1 = __shfl_up_sync(0xffffffffu, i1, o);
            if (lane >= o) { i0 += u0; i1 += u1; }
        }
        int tot0 = __shfl_sync(0xffffffffu, i0, 31);
        s_ex[lane] = i0 - v0;
        s_ex[32 + lane] = i1 - v1 + tot0;
    }
    __syncthreads();
    int off = s_ex[blockIdx.x];
    int gid = blockIdx.x * SCAN_B + tid;
    if (gid < N_NODES) {
        int rp = g_rowptr[gid + 1] + off;
        g_rowptr[gid + 1] = rp;
        if (gid + 1 < N_NODES) g_cursor[gid + 1] = rp;
    }
    if (gid == 0) { g_rowptr[0] = 0; g_cursor[0] = 0; }
}

__global__ void fill_kernel(const int* __restrict__ eidx) {
    int e = blockIdx.x * blockDim.x + threadIdx.x;
    if (e >= N_EDGES) return;
    int s = __ldg(&eidx[e]);
    int d = __ldg(&eidx[N_EDGES + e]);
    int slot = atomicAdd(&g_cursor[d], 1);
    g_esrc[slot] = s;
}

// ---------------------------------------------------------------------------
// Gather-side mean aggregation: one warp per dst node, fp32 rows,
// writes tf32-rounded mean (GEMM stages it with cp.async, no cvt there).
// ---------------------------------------------------------------------------
template <int LAYER>
__global__ void gather_kernel(const float* __restrict__ x_in) {
    int warp = (blockIdx.x * blockDim.x + threadIdx.x) >> 5;
    int lane = threadIdx.x & 31;
    if (warp >= N_NODES) return;

    const float* feat = (LAYER == 1) ? x_in : g_htf;

    int beg = __ldg(&g_rowptr[warp]);
    int end = __ldg(&g_rowptr[warp + 1]);

    float4 acc = make_float4(0.f, 0.f, 0.f, 0.f);
    int j = beg;
    for (; j + 4 <= end; j += 4) {
        int s0 = __ldg(&g_esrc[j + 0]);
        int s1 = __ldg(&g_esrc[j + 1]);
        int s2 = __ldg(&g_esrc[j + 2]);
        int s3 = __ldg(&g_esrc[j + 3]);
        float4 v0 = __ldg(reinterpret_cast<const float4*>(feat + (size_t)s0 * D) + lane);
        float4 v1 = __ldg(reinterpret_cast<const float4*>(feat + (size_t)s1 * D) + lane);
        float4 v2 = __ldg(reinterpret_cast<const float4*>(feat + (size_t)s2 * D) + lane);
        float4 v3 = __ldg(reinterpret_cast<const float4*>(feat + (size_t)s3 * D) + lane);
        acc.x += (v0.x + v1.x) + (v2.x + v3.x);
        acc.y += (v0.y + v1.y) + (v2.y + v3.y);
        acc.z += (v0.z + v1.z) + (v2.z + v3.z);
        acc.w += (v0.w + v1.w) + (v2.w + v3.w);
    }
    for (; j < end; j++) {
        int s = __ldg(&g_esrc[j]);
        float4 v = __ldg(reinterpret_cast<const float4*>(feat + (size_t)s * D) + lane);
        acc.x += v.x; acc.y += v.y; acc.z += v.z; acc.w += v.w;
    }

    float inv = 1.0f / fmaxf((float)(end - beg), 1.0f);
    acc.x = to_tf32(acc.x * inv); acc.y = to_tf32(acc.y * inv);
    acc.z = to_tf32(acc.z * inv); acc.w = to_tf32(acc.w * inv);
    reinterpret_cast<float4*>(g_mean + (size_t)warp * D)[lane] = acc;
}

// ---------------------------------------------------------------------------
// tf32 mma.sync GEMM: out = mean @ Wl + feat @ Wr + b (+relu L1)
// CTA = 128 rows x 128 cols, occ 1 (proven best shell). All operands are
// PRE-ROUNDED tf32 in global -> staging is pure cp.async.cg 16B (no regs,
// no cvt, no LDG->STS round trip). Buffers padded: no bounds checks.
// 4x2 warp grid, each warp m32 x n64.
// ---------------------------------------------------------------------------
#define ASA 132
#define WSB 136
#define TCSM ((128 * ASA + 128 * WSB) * 4)   // 134 KB

__device__ __forceinline__ void mma_tf32(float c[4], uint32_t a0, uint32_t a1,
                                         uint32_t a2, uint32_t a3,
                                         uint32_t b0, uint32_t b1) {
    asm volatile(
        "mma.sync.aligned.m16n8k8.row.col.f32.tf32.tf32.f32 "
        "{%0,%1,%2,%3}, {%4,%5,%6,%7}, {%8,%9}, {%0,%1,%2,%3};"
        : "+f"(c[0]), "+f"(c[1]), "+f"(c[2]), "+f"(c[3])
        : "r"(a0), "r"(a1), "r"(a2), "r"(a3), "r"(b0), "r"(b1));
}

template <int LAYER>
__global__ void __launch_bounds__(256, 1)
sage_gemm_mma(const float* __restrict__ bias, float* __restrict__ d_out) {
    extern __shared__ float sm[];
    float* sA = sm;                 // [128][ASA]
    float* sW = sm + 128 * ASA;     // [128][WSB]

    int tid = threadIdx.x;
    int wid = tid >> 5;
    int lane = tid & 31;
    int gid = lane >> 2;            // 0..7
    int tig = lane & 3;             // 0..3
    int mw = wid >> 1;              // 0..3: m strip of 32 rows
    int nw = wid & 1;               // 0..1: n strip of 64 cols
    int base = blockIdx.x * 128;

    const float* Wl = g_Wtf + (LAYER == 1 ? 0 : 2) * D * D;
    const float* Wr = g_Wtf + (LAYER == 1 ? 1 : 3) * D * D;

    float c[2][8][4];
#pragma unroll
    for (int mt = 0; mt < 2; mt++)
#pragma unroll
        for (int nt = 0; nt < 8; nt++)
#pragma unroll
            for (int q = 0; q < 4; q++) c[mt][nt][q] = 0.f;

#pragma unroll
    for (int pass = 0; pass < 2; pass++) {
        const float* Asrc = (pass == 0) ? g_mean
                          : (LAYER == 1) ? g_xtf : g_htf;
        const float* Wsrc = (pass == 0) ? Wl : Wr;

        if (pass) __syncthreads();   // all warps done reading pass-0 tiles

        // Stage A + W: pure async copies (pre-rounded, padded -> no checks)
        for (int e = tid; e < 128 * 32; e += 256) {
            int r = e >> 5, c4 = e & 31;
            cp16(sA + r * ASA + c4 * 4, Asrc + (size_t)(base + r) * D + c4 * 4);
            cp16(sW + r * WSB + c4 * 4, Wsrc + (size_t)r * D + c4 * 4);
        }
        CP_COMMIT();
        CP_WAIT0();
        __syncthreads();

        const float* Awarp = sA + (mw * 32 + gid) * ASA + tig;
#pragma unroll 4
        for (int ks = 0; ks < 16; ks++) {
            uint32_t a[2][4];
#pragma unroll
            for (int mt = 0; mt < 2; mt++) {
                const float* ap = Awarp + mt * 16 * ASA + ks * 8;
                a[mt][0] = __float_as_uint(ap[0]);
                a[mt][1] = __float_as_uint(ap[8 * ASA]);
                a[mt][2] = __float_as_uint(ap[4]);
                a[mt][3] = __float_as_uint(ap[8 * ASA + 4]);
            }
            const float* bp = sW + (ks * 8 + tig) * WSB + nw * 64 + gid;
#pragma unroll
            for (int nt = 0; nt < 8; nt++) {
                uint32_t b0 = __float_as_uint(bp[nt * 8]);
                uint32_t b1 = __float_as_uint(bp[4 * WSB + nt * 8]);
                mma_tf32(c[0][nt], a[0][0], a[0][1], a[0][2], a[0][3], b0, b1);
                mma_tf32(c[1][nt], a[1][0], a[1][1], a[1][2], a[1][3], b0, b1);
            }
        }
    }

    // Epilogue: bias (+relu); L1 -> g_htf (tf32-rounded), L2 -> d_out (fp32)
#pragma unroll
    for (int mt = 0; mt < 2; mt++) {
        int row0 = base + mw * 32 + mt * 16 + gid;
#pragma unroll
        for (int nt = 0; nt < 8; nt++) {
            int col = nw * 64 + nt * 8 + 2 * tig;
            float2 bb = *reinterpret_cast<const float2*>(bias + col);
            float o0 = c[mt][nt][0] + bb.x, o1 = c[mt][nt][1] + bb.y;
            float o2 = c[mt][nt][2] + bb.x, o3 = c[mt][nt][3] + bb.y;
            if (LAYER == 1) {
                o0 = to_tf32(fmaxf(o0, 0.f)); o1 = to_tf32(fmaxf(o1, 0.f));
                o2 = to_tf32(fmaxf(o2, 0.f)); o3 = to_tf32(fmaxf(o3, 0.f));
                if (row0 < N_NODES)
                    *reinterpret_cast<float2*>(g_htf + (size_t)row0 * D + col) = make_float2(o0, o1);
                if (row0 + 8 < N_NODES)
                    *reinterpret_cast<float2*>(g_htf + (size_t)(row0 + 8) * D + col) = make_float2(o2, o3);
            } else {
                if (row0 < N_NODES)
                    *reinterpret_cast<float2*>(d_out + (size_t)row0 * D + col) = make_float2(o0, o1);
                if (row0 + 8 < N_NODES)
                    *reinterpret_cast<float2*>(d_out + (size_t)(row0 + 8) * D + col) = make_float2(o2, o3);
            }
        }
    }
}

// ---------------------------------------------------------------------------
extern "C" void kernel_launch(void* const* d_in, const int* in_sizes, int n_in,
                              void* d_out, int out_size) {
    const float* x       = (const float*)d_in[0];
    const int* ei        = (const int*)d_in[1];   // int32 (JAX x64 disabled)
    const float* Wl1     = (const float*)d_in[2];
    const float* Wr1     = (const float*)d_in[3];
    const float* b1      = (const float*)d_in[4];
    const float* Wl2     = (const float*)d_in[5];
    const float* Wr2     = (const float*)d_in[6];
    const float* b2      = (const float*)d_in[7];
    float* out           = (float*)d_out;

    cudaFuncSetAttribute(sage_gemm_mma<1>,
                         cudaFuncAttributeMaxDynamicSharedMemorySize, TCSM);
    cudaFuncSetAttribute(sage_gemm_mma<2>,
                         cudaFuncAttributeMaxDynamicSharedMemorySize, TCSM);

    int eb = (N_EDGES + 255) / 256;
    int gather_blocks = (N_NODES * 32 + 255) / 256;
    int gemm_blocks = (N_NODES + 127) / 128;

    // Prep (x/W tf32 rounding + deg zero) + CSR build
    prep_kernel<<<((N_NODES * D / 4) + 255) / 256, 256>>>(x, Wl1, Wr1, Wl2, Wr2);
    hist_kernel<<<eb, 256>>>(ei);
    scan_block<<<NB, SCAN_B>>>();
    scan_add<<<NB, SCAN_B>>>();
    fill_kernel<<<eb, 256>>>(ei);

    // Layer 1
    gather_kernel<1><<<gather_blocks, 256>>>(x);
    sage_gemm_mma<1><<<gemm_blocks, 256, TCSM>>>(b1, out);

    // Layer 2
    gather_kernel<2><<<gather_blocks, 256>>>(x);
    sage_gemm_mma<2><<<gemm_blocks, 256, TCSM>>>(b2, out);
}

// round 16
// speedup vs baseline: 1.0963x; 1.0257x over previous
#include <cuda_runtime.h>
#include <cuda_bf16.h>
#include <cuda_fp16.h>
#include <cstdint>

#define N_NODES 50000
#define N_PAD   50048          // padded rows so GEMM staging needs no bounds checks
#define N_EDGES 600000
#define D 128
#define SCAN_B 1024
#define NB ((N_NODES + SCAN_B - 1) / SCAN_B)   // 49
#define NBLK ((N_NODES + 127) / 128)           // 391 row blocks
#define GEMM_GRID 152                          // 1 persistent CTA per SM

// ---------------------------------------------------------------------------
// Scratch (allocation-free rule: __device__ globals; .bss zero-initialized,
// pad rows [50000,50048) are never written -> stay zero, never NaN)
// ---------------------------------------------------------------------------
__device__ float g_mean[(size_t)N_PAD * D];   // gather out, tf32-rounded
__device__ float g_xtf[(size_t)N_PAD * D];    // x, tf32-rounded
__device__ float g_htf[(size_t)N_PAD * D];    // layer-1 activations, tf32-rounded
__device__ float g_Wtf[4 * D * D];            // Wl1,Wr1,Wl2,Wr2 tf32-rounded
__device__ int   g_deg[N_NODES];              // zeroed by scan_block after read
__device__ int   g_cursor[N_NODES];
__device__ int   g_rowptr[N_NODES + 1];
__device__ int   g_bsum[NB];
__device__ int   g_esrc[N_EDGES];

__device__ __forceinline__ float to_tf32(float f) {
    float r;
    asm("cvt.rna.tf32.f32 %0, %1;" : "=f"(r) : "f"(f));
    return r;
}

__device__ __forceinline__ void cp16(void* s, const void* g) {
    uint32_t sa = (uint32_t)__cvta_generic_to_shared(s);
    asm volatile("cp.async.cg.shared.global [%0], [%1], 16;"
                 :: "r"(sa), "l"(g) : "memory");
}
#define CP_COMMIT() asm volatile("cp.async.commit_group;" ::: "memory")
#define CP_WAIT0()  asm volatile("cp.async.wait_group 0;" ::: "memory")

// ---------------------------------------------------------------------------
// Prep + hist fused (1 launch): round x and W's to tf32; histogram degrees.
// g_deg needs no pre-zero: .bss on first call, re-zeroed by scan_block after.
// ---------------------------------------------------------------------------
__global__ void prep_hist(const float* __restrict__ x,
                          const float* __restrict__ Wl1, const float* __restrict__ Wr1,
                          const float* __restrict__ Wl2, const float* __restrict__ Wr2,
                          const int* __restrict__ eidx) {
    int i = blockIdx.x * blockDim.x + threadIdx.x;   // float4 units
    const int XN = (N_NODES * D) / 4;                // 1.6M
    if (i < XN) {
        float4 v = __ldg(reinterpret_cast<const float4*>(x) + i);
        v.x = to_tf32(v.x); v.y = to_tf32(v.y);
        v.z = to_tf32(v.z); v.w = to_tf32(v.w);
        reinterpret_cast<float4*>(g_xtf)[i] = v;
    }
    const int WN = D * D / 4;                        // 4096 per matrix
    if (i < 4 * WN) {
        int mat = i / WN, r = i % WN;
        const float* W = (mat == 0) ? Wl1 : (mat == 1) ? Wr1 : (mat == 2) ? Wl2 : Wr2;
        float4 v = __ldg(reinterpret_cast<const float4*>(W) + r);
        v.x = to_tf32(v.x); v.y = to_tf32(v.y);
        v.z = to_tf32(v.z); v.w = to_tf32(v.w);
        reinterpret_cast<float4*>(g_Wtf)[i] = v;
    }
    if (i < N_EDGES) atomicAdd(&g_deg[__ldg(&eidx[N_EDGES + i])], 1);
}

// ---------------------------------------------------------------------------
// Scan (coalesced); scan_block re-zeros g_deg after reading (replay-safe).
// ---------------------------------------------------------------------------
__global__ void scan_block() {
    __shared__ int wsum[32];
    int tid = threadIdx.x, lane = tid & 31, w = tid >> 5;
    int gid = blockIdx.x * SCAN_B + tid;
    int v = 0;
    if (gid < N_NODES) { v = g_deg[gid]; g_deg[gid] = 0; }
    int inc = v;
#pragma unroll
    for (int o = 1; o < 32; o <<= 1) {
        int u = __shfl_up_sync(0xffffffffu, inc, o);
        if (lane >= o) inc += u;
    }
    if (lane == 31) wsum[w] = inc;
    __syncthreads();
    if (w == 0) {
        int t = wsum[lane];
        int i2 = t;
#pragma unroll
        for (int o = 1; o < 32; o <<= 1) {
            int u = __shfl_up_sync(0xffffffffu, i2, o);
            if (lane >= o) i2 += u;
        }
        wsum[lane] = i2 - t;   // exclusive warp offsets
    }
    __syncthreads();
    int incl = wsum[w] + inc;
    if (gid < N_NODES) g_rowptr[gid + 1] = incl;
    if (tid == SCAN_B - 1) g_bsum[blockIdx.x] = incl;
}

__global__ void scan_add() {
    __shared__ int s_ex[64];
    int tid = threadIdx.x, lane = tid & 31;
    if (tid < 32) {
        int v0 = (lane < NB) ? g_bsum[lane] : 0;
        int v1 = (32 + lane < NB) ? g_bsum[32 + lane] : 0;
        int i0 = v0, i1 = v1;
#pragma unroll
        for (int o = 1; o < 32; o <<= 1) {
            int u0 = __shfl_up_sync(0xffffffffu, i0, o);
            int u1 = __shfl_up_sync(0xffffffffu, i1, o);
            if (lane >= o) { i0 += u0; i1 += u1; }
        }
        int tot0 = __shfl_sync(0xffffffffu, i0, 31);
        s_ex[lane] = i0 - v0;
        s_ex[32 + lane] = i1 - v1 + tot0;
    }
    __syncthreads();
    int off = s_ex[blockIdx.x];
    int gid = blockIdx.x * SCAN_B + tid;
    if (gid < N_NODES) {
        int rp = g_rowptr[gid + 1] + off;
        g_rowptr[gid + 1] = rp;
        if (gid + 1 < N_NODES) g_cursor[gid + 1] = rp;
    }
    if (gid == 0) { g_rowptr[0] = 0; g_cursor[0] = 0; }
}

__global__ void fill_kernel(const int* __restrict__ eidx) {
    int e = blockIdx.x * blockDim.x + threadIdx.x;
    if (e >= N_EDGES) return;
    int s = __ldg(&eidx[e]);
    int d = __ldg(&eidx[N_EDGES + e]);
    int slot = atomicAdd(&g_cursor[d], 1);
    g_esrc[slot] = s;
}

// ---------------------------------------------------------------------------
// Gather-side mean aggregation: one warp per dst node, fp32 rows,
// writes tf32-rounded mean.
// ---------------------------------------------------------------------------
template <int LAYER>
__global__ void gather_kernel(const float* __restrict__ x_in) {
    int warp = (blockIdx.x * blockDim.x + threadIdx.x) >> 5;
    int lane = threadIdx.x & 31;
    if (warp >= N_NODES) return;

    const float* feat = (LAYER == 1) ? x_in : g_htf;

    int beg = __ldg(&g_rowptr[warp]);
    int end = __ldg(&g_rowptr[warp + 1]);

    float4 acc = make_float4(0.f, 0.f, 0.f, 0.f);
    int j = beg;
    for (; j + 4 <= end; j += 4) {
        int s0 = __ldg(&g_esrc[j + 0]);
        int s1 = __ldg(&g_esrc[j + 1]);
        int s2 = __ldg(&g_esrc[j + 2]);
        int s3 = __ldg(&g_esrc[j + 3]);
        float4 v0 = __ldg(reinterpret_cast<const float4*>(feat + (size_t)s0 * D) + lane);
        float4 v1 = __ldg(reinterpret_cast<const float4*>(feat + (size_t)s1 * D) + lane);
        float4 v2 = __ldg(reinterpret_cast<const float4*>(feat + (size_t)s2 * D) + lane);
        float4 v3 = __ldg(reinterpret_cast<const float4*>(feat + (size_t)s3 * D) + lane);
        acc.x += (v0.x + v1.x) + (v2.x + v3.x);
        acc.y += (v0.y + v1.y) + (v2.y + v3.y);
        acc.z += (v0.z + v1.z) + (v2.z + v3.z);
        acc.w += (v0.w + v1.w) + (v2.w + v3.w);
    }
    for (; j < end; j++) {
        int s = __ldg(&g_esrc[j]);
        float4 v = __ldg(reinterpret_cast<const float4*>(feat + (size_t)s * D) + lane);
        acc.x += v.x; acc.y += v.y; acc.z += v.z; acc.w += v.w;
    }

    float inv = 1.0f / fmaxf((float)(end - beg), 1.0f);
    acc.x = to_tf32(acc.x * inv); acc.y = to_tf32(acc.y * inv);
    acc.z = to_tf32(acc.z * inv); acc.w = to_tf32(acc.w * inv);
    reinterpret_cast<float4*>(g_mean + (size_t)warp * D)[lane] = acc;
}

// ---------------------------------------------------------------------------
// Persistent tf32 mma GEMM: out = mean @ Wl + feat @ Wr + b (+relu L1)
// 152 CTAs (1/SM). BOTH W tiles cp.async-staged ONCE per CTA (139 KB),
// then loop over row blocks staging only A (68 KB/pass). Cuts W traffic
// 54 MB -> 20 MB vs per-block staging. smem total 202 KB (occ 1).
// 4x2 warp grid, each warp m32 x n64. All operands pre-rounded tf32.
// ---------------------------------------------------------------------------
#define ASA 132
#define WSB 136
#define TCSM ((128 * ASA + 2 * 128 * WSB) * 4)   // 202 KB

__device__ __forceinline__ void mma_tf32(float c[4], uint32_t a0, uint32_t a1,
                                         uint32_t a2, uint32_t a3,
                                         uint32_t b0, uint32_t b1) {
    asm volatile(
        "mma.sync.aligned.m16n8k8.row.col.f32.tf32.tf32.f32 "
        "{%0,%1,%2,%3}, {%4,%5,%6,%7}, {%8,%9}, {%0,%1,%2,%3};"
        : "+f"(c[0]), "+f"(c[1]), "+f"(c[2]), "+f"(c[3])
        : "r"(a0), "r"(a1), "r"(a2), "r"(a3), "r"(b0), "r"(b1));
}

template <int LAYER>
__global__ void __launch_bounds__(256, 1)
sage_gemm_mma(const float* __restrict__ bias, float* __restrict__ d_out) {
    extern __shared__ float sm[];
    float* sA  = sm;                    // [128][ASA]
    float* sW0 = sm + 128 * ASA;        // [128][WSB]
    float* sW1 = sW0 + 128 * WSB;       // [128][WSB]

    int tid = threadIdx.x;
    int wid = tid >> 5;
    int lane = tid & 31;
    int gid = lane >> 2;            // 0..7
    int tig = lane & 3;             // 0..3
    int mw = wid >> 1;              // 0..3: m strip of 32 rows
    int nw = wid & 1;               // 0..1: n strip of 64 cols

    const float* Wl = g_Wtf + (LAYER == 1 ? 0 : 2) * D * D;
    const float* Wr = g_Wtf + (LAYER == 1 ? 1 : 3) * D * D;
    const float* Afeat = (LAYER == 1) ? g_xtf : g_htf;

    // Stage BOTH weight tiles once
    for (int e = tid; e < 128 * 32; e += 256) {
        int r = e >> 5, c4 = e & 31;
        cp16(sW0 + r * WSB + c4 * 4, Wl + (size_t)r * D + c4 * 4);
        cp16(sW1 + r * WSB + c4 * 4, Wr + (size_t)r * D + c4 * 4);
    }
    CP_COMMIT();
    CP_WAIT0();
    __syncthreads();

    for (int blk = blockIdx.x; blk < NBLK; blk += GEMM_GRID) {
        int base = blk * 128;

        float c[2][8][4];
#pragma unroll
        for (int mt = 0; mt < 2; mt++)
#pragma unroll
            for (int nt = 0; nt < 8; nt++)
#pragma unroll
                for (int q = 0; q < 4; q++) c[mt][nt][q] = 0.f;

#pragma unroll
        for (int pass = 0; pass < 2; pass++) {
            const float* Asrc = (pass == 0) ? g_mean : Afeat;
            const float* sW = (pass == 0) ? sW0 : sW1;

            // Stage A for this pass (padded buffers: no bounds checks)
            for (int e = tid; e < 128 * 32; e += 256) {
                int r = e >> 5, c4 = e & 31;
                cp16(sA + r * ASA + c4 * 4, Asrc + (size_t)(base + r) * D + c4 * 4);
            }
            CP_COMMIT();
            CP_WAIT0();
            __syncthreads();

            const float* Awarp = sA + (mw * 32 + gid) * ASA + tig;
#pragma unroll 4
            for (int ks = 0; ks < 16; ks++) {
                uint32_t a[2][4];
#pragma unroll
                for (int mt = 0; mt < 2; mt++) {
                    const float* ap = Awarp + mt * 16 * ASA + ks * 8;
                    a[mt][0] = __float_as_uint(ap[0]);
                    a[mt][1] = __float_as_uint(ap[8 * ASA]);
                    a[mt][2] = __float_as_uint(ap[4]);
                    a[mt][3] = __float_as_uint(ap[8 * ASA + 4]);
                }
                const float* bp = sW + (ks * 8 + tig) * WSB + nw * 64 + gid;
#pragma unroll
                for (int nt = 0; nt < 8; nt++) {
                    uint32_t b0 = __float_as_uint(bp[nt * 8]);
                    uint32_t b1 = __float_as_uint(bp[4 * WSB + nt * 8]);
                    mma_tf32(c[0][nt], a[0][0], a[0][1], a[0][2], a[0][3], b0, b1);
                    mma_tf32(c[1][nt], a[1][0], a[1][1], a[1][2], a[1][3], b0, b1);
                }
            }
            __syncthreads();   // sA fully consumed before next staging
        }

        // Epilogue: bias (+relu); L1 -> g_htf (tf32-rounded), L2 -> d_out
#pragma unroll
        for (int mt = 0; mt < 2; mt++) {
            int row0 = base + mw * 32 + mt * 16 + gid;
#pragma unroll
            for (int nt = 0; nt < 8; nt++) {
                int col = nw * 64 + nt * 8 + 2 * tig;
                float2 bb = *reinterpret_cast<const float2*>(bias + col);
                float o0 = c[mt][nt][0] + bb.x, o1 = c[mt][nt][1] + bb.y;
                float o2 = c[mt][nt][2] + bb.x, o3 = c[mt][nt][3] + bb.y;
                if (LAYER == 1) {
                    o0 = to_tf32(fmaxf(o0, 0.f)); o1 = to_tf32(fmaxf(o1, 0.f));
                    o2 = to_tf32(fmaxf(o2, 0.f)); o3 = to_tf32(fmaxf(o3, 0.f));
                    if (row0 < N_NODES)
                        *reinterpret_cast<float2*>(g_htf + (size_t)row0 * D + col) = make_float2(o0, o1);
                    if (row0 + 8 < N_NODES)
                        *reinterpret_cast<float2*>(g_htf + (size_t)(row0 + 8) * D + col) = make_float2(o2, o3);
                } else {
                    if (row0 < N_NODES)
                        *reinterpret_cast<float2*>(d_out + (size_t)row0 * D + col) = make_float2(o0, o1);
                    if (row0 + 8 < N_NODES)
                        *reinterpret_cast<float2*>(d_out + (size_t)(row0 + 8) * D + col) = make_float2(o2, o3);
                }
            }
        }
    }
}

// ---------------------------------------------------------------------------
extern "C" void kernel_launch(void* const* d_in, const int* in_sizes, int n_in,
                              void* d_out, int out_size) {
    const float* x       = (const float*)d_in[0];
    const int* ei        = (const int*)d_in[1];   // int32 (JAX x64 disabled)
    const float* Wl1     = (const float*)d_in[2];
    const float* Wr1     = (const float*)d_in[3];
    const float* b1      = (const float*)d_in[4];
    const float* Wl2     = (const float*)d_in[5];
    const float* Wr2     = (const float*)d_in[6];
    const float* b2      = (const float*)d_in[7];
    float* out           = (float*)d_out;

    cudaFuncSetAttribute(sage_gemm_mma<1>,
                         cudaFuncAttributeMaxDynamicSharedMemorySize, TCSM);
    cudaFuncSetAttribute(sage_gemm_mma<2>,
                         cudaFuncAttributeMaxDynamicSharedMemorySize, TCSM);

    int eb = (N_EDGES + 255) / 256;
    int gather_blocks = (N_NODES * 32 + 255) / 256;

    // Prep (x/W rounding) + hist fused; scan re-zeros g_deg; fill
    prep_hist<<<((N_NODES * D / 4) + 255) / 256, 256>>>(x, Wl1, Wr1, Wl2, Wr2, ei);
    scan_block<<<NB, SCAN_B>>>();
    scan_add<<<NB, SCAN_B>>>();
    fill_kernel<<<eb, 256>>>(ei);

    // Layer 1
    gather_kernel<1><<<gather_blocks, 256>>>(x);
    sage_gemm_mma<1><<<GEMM_GRID, 256, TCSM>>>(b1, out);

    // Layer 2
    gather_kernel<2><<<gather_blocks, 256>>>(x);
    sage_gemm_mma<2><<<GEMM_GRID, 256, TCSM>>>(b2, out);
}